// round 9
// baseline (speedup 1.0000x reference)
#include <cuda_runtime.h>
#include <cstdint>

#define NNODES 50000
#define NEDGES 800000
#define CDIM 256
#define FIN 768

#define BM 128
#define BN 128
#define KCH 16
#define PITCH 20                    // floats; conflict-free fragment loads
#define STG (BM * PITCH)            // floats per stage buffer (2560)
#define STGB (STG * 4)              // bytes per stage buffer (10240)
#define NSTAGE 3
#define SMEM_BYTES (2 * NSTAGE * STGB)   // 61440

// Scratch (allocation-free rule: device globals)
__device__ float g_dinv[NNODES];
__device__ int   g_deg[NNODES];
__device__ int   g_off[NNODES + 1];
__device__ int   g_cur[NNODES];
__device__ int   g_csrc[NEDGES];
__device__ float g_hs [NNODES * CDIM];   // GEMM output h (unscaled)
__device__ float g_h1 [NNODES * CDIM];   // layer-1 activation (tf32-rounded)
__device__ float g_WT1[CDIM * FIN];
__device__ float g_WT2[CDIM * CDIM];

__device__ __forceinline__ uint32_t smem_u32(const void* p) {
    uint32_t a;
    asm("{ .reg .u64 t; cvta.to.shared.u64 t, %1; cvt.u32.u64 %0, t; }"
        : "=r"(a) : "l"(p));
    return a;
}
__device__ __forceinline__ uint32_t f2tf32(float f) {
    uint32_t u;
    asm("cvt.rna.tf32.f32 %0, %1;" : "=r"(u) : "f"(f));
    return u;
}
__device__ __forceinline__ void mma_tf32(float* c, const uint32_t* a, const uint32_t* b) {
    asm volatile(
        "mma.sync.aligned.m16n8k8.row.col.f32.tf32.tf32.f32 "
        "{%0,%1,%2,%3}, {%4,%5,%6,%7}, {%8,%9}, {%0,%1,%2,%3};"
        : "+f"(c[0]), "+f"(c[1]), "+f"(c[2]), "+f"(c[3])
        : "r"(a[0]), "r"(a[1]), "r"(a[2]), "r"(a[3]), "r"(b[0]), "r"(b[1]));
}

// ---------------------------------------------------------------------------
__global__ void zero_int_k(int* __restrict__ p, int n) {
    int i = blockIdx.x * blockDim.x + threadIdx.x;
    if (i < n) p[i] = 0;
}
__global__ void degree_k(const int* __restrict__ dst, int E4) {
    int i = blockIdx.x * blockDim.x + threadIdx.x;
    if (i < E4) {
        int4 d = reinterpret_cast<const int4*>(dst)[i];
        atomicAdd(&g_deg[d.x], 1);
        atomicAdd(&g_deg[d.y], 1);
        atomicAdd(&g_deg[d.z], 1);
        atomicAdd(&g_deg[d.w], 1);
    }
}
__global__ void dinv_k(int n) {
    int i = blockIdx.x * blockDim.x + threadIdx.x;
    if (i < n) g_dinv[i] = rsqrtf((float)g_deg[i] + 1.0f);  // +1 = self loop
}

__global__ void scan_k() {
    __shared__ int sums[1024];
    const int T = 1024;
    const int chunk = (NNODES + T - 1) / T;
    int t = threadIdx.x;
    int base = t * chunk;
    int s = 0;
    for (int j = 0; j < chunk; j++) {
        int i = base + j;
        if (i < NNODES) s += g_deg[i];
    }
    sums[t] = s;
    __syncthreads();
    for (int d = 1; d < T; d <<= 1) {
        int v = (t >= d) ? sums[t - d] : 0;
        __syncthreads();
        sums[t] += v;
        __syncthreads();
    }
    int run = (t == 0) ? 0 : sums[t - 1];
    for (int j = 0; j < chunk; j++) {
        int i = base + j;
        if (i < NNODES) {
            g_off[i] = run;
            g_cur[i] = run;
            run += g_deg[i];
        }
    }
    if (t == T - 1) g_off[NNODES] = run;
}

__global__ void csr_fill_k(const int* __restrict__ src,
                           const int* __restrict__ dst, int E) {
    int e = blockIdx.x * blockDim.x + threadIdx.x;
    if (e < E) {
        int p = atomicAdd(&g_cur[dst[e]], 1);
        g_csrc[p] = src[e];
    }
}

// Both weight transposes in ONE launch (keeps gemm1 in the ncu capture slot).
__global__ void transpose_both_k(const float* __restrict__ W1,
                                 const float* __restrict__ W2) {
    int idx = blockIdx.x * blockDim.x + threadIdx.x;
    if (idx < FIN * CDIM) {
        int n = idx & (CDIM - 1);
        int k = idx >> 8;
        g_WT1[(size_t)n * FIN + k] =
            __uint_as_float(f2tf32(W1[(size_t)k * CDIM + n]));
    } else {
        idx -= FIN * CDIM;
        if (idx < CDIM * CDIM) {
            int n = idx & (CDIM - 1);
            int k = idx >> 8;
            g_WT2[(size_t)n * CDIM + k] =
                __uint_as_float(f2tf32(W2[(size_t)k * CDIM + n]));
        }
    }
}

// ---------------------------------------------------------------------------
// C[M,256] = A[M,K] @ WT^T  (dinv applied in agg_k)
// 128x128 CTA tile, 8 warps (2x4), 64x32 warp tiles.
// cp.async 3-stage pipeline, ONE __syncthreads per K-chunk.
// ---------------------------------------------------------------------------
template <bool CVT>
__global__ __launch_bounds__(256, 2) void gemm_mma_k(
    const float* __restrict__ A, const float* __restrict__ WT,
    float* __restrict__ C, int M, int K)
{
    extern __shared__ float smem[];
    float* Asm = smem;                    // NSTAGE x STG
    float* Bsm = smem + NSTAGE * STG;     // NSTAGE x STG

    const int tid  = threadIdx.x;
    const int lane = tid & 31;
    const int wid  = tid >> 5;
    const int wm   = wid & 1;
    const int wn   = wid >> 1;
    const int gq   = lane >> 2;
    const int cq   = lane & 3;
    const int row0 = blockIdx.y * BM;
    const int col0 = blockIdx.x * BN;

    const uint32_t asb = smem_u32(Asm);
    const uint32_t bsb = smem_u32(Bsm);

    float acc[4][4][4];
    #pragma unroll
    for (int mt = 0; mt < 4; mt++)
        #pragma unroll
        for (int nt = 0; nt < 4; nt++)
            #pragma unroll
            for (int q = 0; q < 4; q++) acc[mt][nt][q] = 0.f;

    const int nkc = K / KCH;

    auto issue = [&](int kc, int buf) {
        const int koff = kc * KCH;
        #pragma unroll
        for (int t = 0; t < 2; t++) {
            int idx = tid + t * 256;
            int r   = idx >> 2;
            int kq  = (idx & 3) * 4;
            uint32_t soff = (uint32_t)((r * PITCH + kq) * 4) + (uint32_t)buf * STGB;
            int gr = row0 + r;
            const float* srcA = A + (size_t)(gr < M ? gr : M - 1) * K + koff + kq;
            int nb = (gr < M) ? 16 : 0;
            asm volatile("cp.async.ca.shared.global [%0], [%1], 16, %2;"
                         :: "r"(asb + soff), "l"(srcA), "r"(nb));
            const float* srcB = WT + (size_t)(col0 + r) * K + koff + kq;
            asm volatile("cp.async.ca.shared.global [%0], [%1], 16;"
                         :: "r"(bsb + soff), "l"(srcB));
        }
        asm volatile("cp.async.commit_group;" ::: "memory");
    };

    issue(0, 0);
    if (nkc > 1) issue(1, 1);

    int buf = 0;
    for (int kc = 0; kc < nkc; kc++) {
        if (kc + 1 < nkc)
            asm volatile("cp.async.wait_group 1;" ::: "memory");
        else
            asm volatile("cp.async.wait_group 0;" ::: "memory");
        __syncthreads();

        // prefetch 2 ahead into the buffer read at iteration kc-1 (safe: all
        // warps passed the barrier above only after finishing that read)
        if (kc + 2 < nkc) {
            int nb2 = (kc + 2) % NSTAGE;
            issue(kc + 2, nb2);
        }

        const float* Ac = Asm + buf * STG;
        const float* Bc = Bsm + buf * STG;

        #pragma unroll
        for (int k0 = 0; k0 < KCH; k0 += 8) {
            uint32_t bf[4][2];
            #pragma unroll
            for (int nt = 0; nt < 4; nt++) {
                int n = wn * 32 + nt * 8 + gq;
                bf[nt][0] = __float_as_uint(Bc[n * PITCH + k0 + cq]);
                bf[nt][1] = __float_as_uint(Bc[n * PITCH + k0 + cq + 4]);
            }
            #pragma unroll
            for (int mt = 0; mt < 4; mt++) {
                int r = wm * 64 + mt * 16 + gq;
                uint32_t af[4];
                if (CVT) {
                    af[0] = f2tf32(Ac[(r    ) * PITCH + k0 + cq    ]);
                    af[1] = f2tf32(Ac[(r + 8) * PITCH + k0 + cq    ]);
                    af[2] = f2tf32(Ac[(r    ) * PITCH + k0 + cq + 4]);
                    af[3] = f2tf32(Ac[(r + 8) * PITCH + k0 + cq + 4]);
                } else {
                    af[0] = __float_as_uint(Ac[(r    ) * PITCH + k0 + cq    ]);
                    af[1] = __float_as_uint(Ac[(r + 8) * PITCH + k0 + cq    ]);
                    af[2] = __float_as_uint(Ac[(r    ) * PITCH + k0 + cq + 4]);
                    af[3] = __float_as_uint(Ac[(r + 8) * PITCH + k0 + cq + 4]);
                }
                #pragma unroll
                for (int nt = 0; nt < 4; nt++)
                    mma_tf32(acc[mt][nt], af, bf[nt]);
            }
        }
        buf = (buf + 1 == NSTAGE) ? 0 : buf + 1;
    }

    #pragma unroll
    for (int mt = 0; mt < 4; mt++) {
        #pragma unroll
        for (int h = 0; h < 2; h++) {
            int row = row0 + wm * 64 + mt * 16 + gq + h * 8;
            if (row < M) {
                float* cp = C + (size_t)row * CDIM + col0 + wn * 32;
                #pragma unroll
                for (int nt = 0; nt < 4; nt++) {
                    float2 o;
                    o.x = acc[mt][nt][h * 2 + 0];
                    o.y = acc[mt][nt][h * 2 + 1];
                    *reinterpret_cast<float2*>(cp + nt * 8 + cq * 2) = o;
                }
            }
        }
    }
}

// ---------------------------------------------------------------------------
// Fused CSR gather with per-edge dinv[src] + self-loop + dinv[dst] + bias
// ---------------------------------------------------------------------------
__global__ __launch_bounds__(256) void agg_k(const float* __restrict__ b,
                                             float* __restrict__ out,
                                             int relu_round)
{
    int node = blockIdx.x * 4 + (threadIdx.x >> 6);
    if (node >= NNODES) return;
    int lane = threadIdx.x & 63;

    const float4* hs4 = reinterpret_cast<const float4*>(g_hs);
    float di = g_dinv[node];
    float4 self = hs4[(size_t)node * 64 + lane];
    float4 acc;
    acc.x = self.x * di; acc.y = self.y * di;
    acc.z = self.z * di; acc.w = self.w * di;

    int j   = g_off[node];
    int end = g_off[node + 1];
    for (; j + 1 < end; j += 2) {
        int s0 = g_csrc[j];
        int s1 = g_csrc[j + 1];
        float d0 = g_dinv[s0];
        float d1 = g_dinv[s1];
        float4 v0 = hs4[(size_t)s0 * 64 + lane];
        float4 v1 = hs4[(size_t)s1 * 64 + lane];
        acc.x = fmaf(v0.x, d0, acc.x); acc.y = fmaf(v0.y, d0, acc.y);
        acc.z = fmaf(v0.z, d0, acc.z); acc.w = fmaf(v0.w, d0, acc.w);
        acc.x = fmaf(v1.x, d1, acc.x); acc.y = fmaf(v1.y, d1, acc.y);
        acc.z = fmaf(v1.z, d1, acc.z); acc.w = fmaf(v1.w, d1, acc.w);
    }
    if (j < end) {
        int s0 = g_csrc[j];
        float d0 = g_dinv[s0];
        float4 v0 = hs4[(size_t)s0 * 64 + lane];
        acc.x = fmaf(v0.x, d0, acc.x); acc.y = fmaf(v0.y, d0, acc.y);
        acc.z = fmaf(v0.z, d0, acc.z); acc.w = fmaf(v0.w, d0, acc.w);
    }

    const float4 bb = *reinterpret_cast<const float4*>(b + lane * 4);
    float4 o;
    o.x = fmaf(acc.x, di, bb.x);
    o.y = fmaf(acc.y, di, bb.y);
    o.z = fmaf(acc.z, di, bb.z);
    o.w = fmaf(acc.w, di, bb.w);
    if (relu_round) {
        o.x = __uint_as_float(f2tf32(fmaxf(o.x, 0.f)));
        o.y = __uint_as_float(f2tf32(fmaxf(o.y, 0.f)));
        o.z = __uint_as_float(f2tf32(fmaxf(o.z, 0.f)));
        o.w = __uint_as_float(f2tf32(fmaxf(o.w, 0.f)));
    }
    reinterpret_cast<float4*>(out)[(size_t)node * 64 + lane] = o;
}

// ---------------------------------------------------------------------------
extern "C" void kernel_launch(void* const* d_in, const int* in_sizes, int n_in,
                              void* d_out, int out_size)
{
    const float* x  = (const float*)d_in[0];
    const int*   ei = (const int*)  d_in[1];
    const float* W1 = (const float*)d_in[2];
    const float* b1 = (const float*)d_in[3];
    const float* W2 = (const float*)d_in[4];
    const float* b2 = (const float*)d_in[5];
    (void)in_sizes; (void)n_in; (void)out_size;

    const int* src = ei;
    const int* dst = ei + NEDGES;

    float *hs, *h1, *wt1, *wt2;
    int* degp;
    cudaGetSymbolAddress((void**)&hs,  g_hs);
    cudaGetSymbolAddress((void**)&h1,  g_h1);
    cudaGetSymbolAddress((void**)&wt1, g_WT1);
    cudaGetSymbolAddress((void**)&wt2, g_WT2);
    cudaGetSymbolAddress((void**)&degp, g_deg);

    cudaFuncSetAttribute(gemm_mma_k<true>,
                         cudaFuncAttributeMaxDynamicSharedMemorySize, SMEM_BYTES);
    cudaFuncSetAttribute(gemm_mma_k<false>,
                         cudaFuncAttributeMaxDynamicSharedMemorySize, SMEM_BYTES);

    const dim3 gemm_grid(CDIM / BN, (NNODES + BM - 1) / BM);   // (2, 391)
    const int agg_grid = (NNODES + 3) / 4;

    // Order keeps gemm_mma_k<true> in the ncu capture slot.
    transpose_both_k<<<((FIN + CDIM) * CDIM + 255) / 256, 256>>>(W1, W2);      // 0
    zero_int_k<<<(NNODES + 255) / 256, 256>>>(degp, NNODES);                   // 1
    degree_k  <<<(NEDGES / 4 + 255) / 256, 256>>>(dst, NEDGES / 4);            // 2
    gemm_mma_k<true><<<gemm_grid, 256, SMEM_BYTES>>>(x, wt1, hs, NNODES, FIN); // 3 <- ncu
    dinv_k    <<<(NNODES + 255) / 256, 256>>>(NNODES);                         // 4
    scan_k    <<<1, 1024>>>();                                                 // 5
    csr_fill_k<<<(NEDGES + 255) / 256, 256>>>(src, dst, NEDGES);               // 6
    agg_k     <<<agg_grid, 256>>>(b1, h1, 1);                                  // 7
    gemm_mma_k<false><<<gemm_grid, 256, SMEM_BYTES>>>(h1, wt2, hs, NNODES, CDIM); // 8
    agg_k     <<<agg_grid, 256>>>(b2, (float*)d_out, 0);                       // 9
}

// round 10
// speedup vs baseline: 1.0880x; 1.0880x over previous
#include <cuda_runtime.h>
#include <cstdint>

#define NNODES 50000
#define NEDGES 800000
#define CDIM 256
#define FIN 768

#define BM 128
#define BN 128
#define KCH 16
#define PITCH 20                  // floats; conflict-free fragment loads
#define BUFB (BM * PITCH * 4)     // bytes per stage buffer

// Scratch (allocation-free rule: device globals)
__device__ float g_dinv[NNODES];
__device__ int   g_deg[NNODES];
__device__ int   g_off[NNODES + 1];
__device__ int   g_cur[NNODES];
__device__ int   g_csrc[NEDGES];
__device__ float g_hs [NNODES * CDIM];   // GEMM output h (unscaled)
__device__ float g_h1 [NNODES * CDIM];   // layer-1 activation (tf32-rounded)
__device__ float g_WT1[CDIM * FIN];
__device__ float g_WT2[CDIM * CDIM];

__device__ __forceinline__ uint32_t smem_u32(const void* p) {
    uint32_t a;
    asm("{ .reg .u64 t; cvta.to.shared.u64 t, %1; cvt.u32.u64 %0, t; }"
        : "=r"(a) : "l"(p));
    return a;
}
__device__ __forceinline__ uint32_t f2tf32(float f) {
    uint32_t u;
    asm("cvt.rna.tf32.f32 %0, %1;" : "=r"(u) : "f"(f));
    return u;
}
__device__ __forceinline__ void mma_tf32(float* c, const uint32_t* a, const uint32_t* b) {
    asm volatile(
        "mma.sync.aligned.m16n8k8.row.col.f32.tf32.tf32.f32 "
        "{%0,%1,%2,%3}, {%4,%5,%6,%7}, {%8,%9}, {%0,%1,%2,%3};"
        : "+f"(c[0]), "+f"(c[1]), "+f"(c[2]), "+f"(c[3])
        : "r"(a[0]), "r"(a[1]), "r"(a[2]), "r"(a[3]), "r"(b[0]), "r"(b[1]));
}

// ---------------------------------------------------------------------------
__global__ void zero_int_k(int* __restrict__ p, int n) {
    int i = blockIdx.x * blockDim.x + threadIdx.x;
    if (i < n) p[i] = 0;
}
__global__ void degree_k(const int* __restrict__ dst, int E4) {
    int i = blockIdx.x * blockDim.x + threadIdx.x;
    if (i < E4) {
        int4 d = reinterpret_cast<const int4*>(dst)[i];
        atomicAdd(&g_deg[d.x], 1);
        atomicAdd(&g_deg[d.y], 1);
        atomicAdd(&g_deg[d.z], 1);
        atomicAdd(&g_deg[d.w], 1);
    }
}
__global__ void dinv_k(int n) {
    int i = blockIdx.x * blockDim.x + threadIdx.x;
    if (i < n) g_dinv[i] = rsqrtf((float)g_deg[i] + 1.0f);  // +1 = self loop
}

__global__ void scan_k() {
    __shared__ int sums[1024];
    const int T = 1024;
    const int chunk = (NNODES + T - 1) / T;
    int t = threadIdx.x;
    int base = t * chunk;
    int s = 0;
    for (int j = 0; j < chunk; j++) {
        int i = base + j;
        if (i < NNODES) s += g_deg[i];
    }
    sums[t] = s;
    __syncthreads();
    for (int d = 1; d < T; d <<= 1) {
        int v = (t >= d) ? sums[t - d] : 0;
        __syncthreads();
        sums[t] += v;
        __syncthreads();
    }
    int run = (t == 0) ? 0 : sums[t - 1];
    for (int j = 0; j < chunk; j++) {
        int i = base + j;
        if (i < NNODES) {
            g_off[i] = run;
            g_cur[i] = run;
            run += g_deg[i];
        }
    }
    if (t == T - 1) g_off[NNODES] = run;
}

__global__ void csr_fill_k(const int* __restrict__ src,
                           const int* __restrict__ dst, int E) {
    int e = blockIdx.x * blockDim.x + threadIdx.x;
    if (e < E) {
        int p = atomicAdd(&g_cur[dst[e]], 1);
        g_csrc[p] = src[e];
    }
}

// Both weight transposes in ONE launch (keeps gemm1 in the ncu capture slot).
__global__ void transpose_both_k(const float* __restrict__ W1,
                                 const float* __restrict__ W2) {
    int idx = blockIdx.x * blockDim.x + threadIdx.x;
    if (idx < FIN * CDIM) {
        int n = idx & (CDIM - 1);
        int k = idx >> 8;
        g_WT1[(size_t)n * FIN + k] =
            __uint_as_float(f2tf32(W1[(size_t)k * CDIM + n]));
    } else {
        idx -= FIN * CDIM;
        if (idx < CDIM * CDIM) {
            int n = idx & (CDIM - 1);
            int k = idx >> 8;
            g_WT2[(size_t)n * CDIM + k] =
                __uint_as_float(f2tf32(W2[(size_t)k * CDIM + n]));
        }
    }
}

// ---------------------------------------------------------------------------
// C[M,256] = A[M,K] @ WT^T  (dinv applied in agg_k)
// 128x128 CTA tile, 8 warps (2x4), 64x32 warp tiles, cp.async 2-stage.
// (R8 config — best measured: 155us on GEMM1)
// ---------------------------------------------------------------------------
template <bool CVT>
__global__ __launch_bounds__(256, 2) void gemm_mma_k(
    const float* __restrict__ A, const float* __restrict__ WT,
    float* __restrict__ C, int M, int K)
{
    __shared__ float As[2][BM * PITCH];
    __shared__ float Bs[2][BN * PITCH];

    const int tid  = threadIdx.x;
    const int lane = tid & 31;
    const int wid  = tid >> 5;
    const int wm   = wid & 1;
    const int wn   = wid >> 1;
    const int gq   = lane >> 2;
    const int cq   = lane & 3;
    const int row0 = blockIdx.y * BM;
    const int col0 = blockIdx.x * BN;

    const uint32_t asb = smem_u32(&As[0][0]);
    const uint32_t bsb = smem_u32(&Bs[0][0]);

    float acc[4][4][4];
    #pragma unroll
    for (int mt = 0; mt < 4; mt++)
        #pragma unroll
        for (int nt = 0; nt < 4; nt++)
            #pragma unroll
            for (int q = 0; q < 4; q++) acc[mt][nt][q] = 0.f;

    const int nkc = K / KCH;

    auto issue = [&](int kc, int buf) {
        const int koff = kc * KCH;
        #pragma unroll
        for (int t = 0; t < 2; t++) {
            int idx = tid + t * 256;
            int r   = idx >> 2;
            int kq  = (idx & 3) * 4;
            uint32_t soff = (uint32_t)((r * PITCH + kq) * 4) + (uint32_t)buf * BUFB;
            int gr = row0 + r;
            const float* srcA = A + (size_t)(gr < M ? gr : M - 1) * K + koff + kq;
            int nb = (gr < M) ? 16 : 0;
            asm volatile("cp.async.ca.shared.global [%0], [%1], 16, %2;"
                         :: "r"(asb + soff), "l"(srcA), "r"(nb));
            const float* srcB = WT + (size_t)(col0 + r) * K + koff + kq;
            asm volatile("cp.async.ca.shared.global [%0], [%1], 16;"
                         :: "r"(bsb + soff), "l"(srcB));
        }
        asm volatile("cp.async.commit_group;" ::: "memory");
    };

    issue(0, 0);

    for (int kc = 0; kc < nkc; kc++) {
        const int cur = kc & 1;
        const bool more = (kc + 1) < nkc;
        if (more) {
            issue(kc + 1, cur ^ 1);
            asm volatile("cp.async.wait_group 1;" ::: "memory");
        } else {
            asm volatile("cp.async.wait_group 0;" ::: "memory");
        }
        __syncthreads();

        #pragma unroll
        for (int k0 = 0; k0 < KCH; k0 += 8) {
            uint32_t bf[4][2];
            #pragma unroll
            for (int nt = 0; nt < 4; nt++) {
                int n = wn * 32 + nt * 8 + gq;
                bf[nt][0] = __float_as_uint(Bs[cur][n * PITCH + k0 + cq]);
                bf[nt][1] = __float_as_uint(Bs[cur][n * PITCH + k0 + cq + 4]);
            }
            #pragma unroll
            for (int mt = 0; mt < 4; mt++) {
                int r = wm * 64 + mt * 16 + gq;
                uint32_t af[4];
                if (CVT) {
                    af[0] = f2tf32(As[cur][(r    ) * PITCH + k0 + cq    ]);
                    af[1] = f2tf32(As[cur][(r + 8) * PITCH + k0 + cq    ]);
                    af[2] = f2tf32(As[cur][(r    ) * PITCH + k0 + cq + 4]);
                    af[3] = f2tf32(As[cur][(r + 8) * PITCH + k0 + cq + 4]);
                } else {
                    af[0] = __float_as_uint(As[cur][(r    ) * PITCH + k0 + cq    ]);
                    af[1] = __float_as_uint(As[cur][(r + 8) * PITCH + k0 + cq    ]);
                    af[2] = __float_as_uint(As[cur][(r    ) * PITCH + k0 + cq + 4]);
                    af[3] = __float_as_uint(As[cur][(r + 8) * PITCH + k0 + cq + 4]);
                }
                #pragma unroll
                for (int nt = 0; nt < 4; nt++)
                    mma_tf32(acc[mt][nt], af, bf[nt]);
            }
        }
        __syncthreads();
    }

    #pragma unroll
    for (int mt = 0; mt < 4; mt++) {
        #pragma unroll
        for (int h = 0; h < 2; h++) {
            int row = row0 + wm * 64 + mt * 16 + gq + h * 8;
            if (row < M) {
                float* cp = C + (size_t)row * CDIM + col0 + wn * 32;
                #pragma unroll
                for (int nt = 0; nt < 4; nt++) {
                    float2 o;
                    o.x = acc[mt][nt][h * 2 + 0];
                    o.y = acc[mt][nt][h * 2 + 1];
                    *reinterpret_cast<float2*>(cp + nt * 8 + cq * 2) = o;
                }
            }
        }
    }
}

// ---------------------------------------------------------------------------
// Fused CSR gather with per-edge dinv[src] + self-loop + dinv[dst] + bias
// ---------------------------------------------------------------------------
__global__ __launch_bounds__(256) void agg_k(const float* __restrict__ b,
                                             float* __restrict__ out,
                                             int relu_round)
{
    int node = blockIdx.x * 4 + (threadIdx.x >> 6);
    if (node >= NNODES) return;
    int lane = threadIdx.x & 63;

    const float4* hs4 = reinterpret_cast<const float4*>(g_hs);
    float di = g_dinv[node];
    float4 self = hs4[(size_t)node * 64 + lane];
    float4 acc;
    acc.x = self.x * di; acc.y = self.y * di;
    acc.z = self.z * di; acc.w = self.w * di;

    int j   = g_off[node];
    int end = g_off[node + 1];
    for (; j + 1 < end; j += 2) {
        int s0 = g_csrc[j];
        int s1 = g_csrc[j + 1];
        float d0 = g_dinv[s0];
        float d1 = g_dinv[s1];
        float4 v0 = hs4[(size_t)s0 * 64 + lane];
        float4 v1 = hs4[(size_t)s1 * 64 + lane];
        acc.x = fmaf(v0.x, d0, acc.x); acc.y = fmaf(v0.y, d0, acc.y);
        acc.z = fmaf(v0.z, d0, acc.z); acc.w = fmaf(v0.w, d0, acc.w);
        acc.x = fmaf(v1.x, d1, acc.x); acc.y = fmaf(v1.y, d1, acc.y);
        acc.z = fmaf(v1.z, d1, acc.z); acc.w = fmaf(v1.w, d1, acc.w);
    }
    if (j < end) {
        int s0 = g_csrc[j];
        float d0 = g_dinv[s0];
        float4 v0 = hs4[(size_t)s0 * 64 + lane];
        acc.x = fmaf(v0.x, d0, acc.x); acc.y = fmaf(v0.y, d0, acc.y);
        acc.z = fmaf(v0.z, d0, acc.z); acc.w = fmaf(v0.w, d0, acc.w);
    }

    const float4 bb = *reinterpret_cast<const float4*>(b + lane * 4);
    float4 o;
    o.x = fmaf(acc.x, di, bb.x);
    o.y = fmaf(acc.y, di, bb.y);
    o.z = fmaf(acc.z, di, bb.z);
    o.w = fmaf(acc.w, di, bb.w);
    if (relu_round) {
        o.x = __uint_as_float(f2tf32(fmaxf(o.x, 0.f)));
        o.y = __uint_as_float(f2tf32(fmaxf(o.y, 0.f)));
        o.z = __uint_as_float(f2tf32(fmaxf(o.z, 0.f)));
        o.w = __uint_as_float(f2tf32(fmaxf(o.w, 0.f)));
    }
    reinterpret_cast<float4*>(out)[(size_t)node * 64 + lane] = o;
}

// ---------------------------------------------------------------------------
extern "C" void kernel_launch(void* const* d_in, const int* in_sizes, int n_in,
                              void* d_out, int out_size)
{
    const float* x  = (const float*)d_in[0];
    const int*   ei = (const int*)  d_in[1];
    const float* W1 = (const float*)d_in[2];
    const float* b1 = (const float*)d_in[3];
    const float* W2 = (const float*)d_in[4];
    const float* b2 = (const float*)d_in[5];
    (void)in_sizes; (void)n_in; (void)out_size;

    const int* src = ei;
    const int* dst = ei + NEDGES;

    float *hs, *h1, *wt1, *wt2;
    int* degp;
    cudaGetSymbolAddress((void**)&hs,  g_hs);
    cudaGetSymbolAddress((void**)&h1,  g_h1);
    cudaGetSymbolAddress((void**)&wt1, g_WT1);
    cudaGetSymbolAddress((void**)&wt2, g_WT2);
    cudaGetSymbolAddress((void**)&degp, g_deg);

    // Side stream + events for fork/join inside graph capture (created once;
    // no device memory involved).
    static cudaStream_t sB = nullptr;
    static cudaEvent_t evFork = nullptr, evJoin = nullptr;
    if (!sB) {
        cudaStreamCreateWithFlags(&sB, cudaStreamNonBlocking);
        cudaEventCreateWithFlags(&evFork, cudaEventDisableTiming);
        cudaEventCreateWithFlags(&evJoin, cudaEventDisableTiming);
    }

    const dim3 gemm_grid(CDIM / BN, (NNODES + BM - 1) / BM);   // (2, 391)
    const int agg_grid = (NNODES + 3) / 4;

    // Fork side stream off the main (capturing) stream.
    cudaEventRecord(evFork, 0);
    cudaStreamWaitEvent(sB, evFork, 0);

    // Main stream: weights + GEMM1 (independent of graph preprocessing).
    // Launch-call order keeps gemm1 as the 4th launch (ncu capture slot).
    transpose_both_k<<<((FIN + CDIM) * CDIM + 255) / 256, 256>>>(W1, W2);      // 0 main
    zero_int_k<<<(NNODES + 255) / 256, 256, 0, sB>>>(degp, NNODES);            // 1 side
    degree_k  <<<(NEDGES / 4 + 255) / 256, 256, 0, sB>>>(dst, NEDGES / 4);     // 2 side
    gemm_mma_k<true><<<gemm_grid, 256>>>(x, wt1, hs, NNODES, FIN);             // 3 main <- ncu
    dinv_k    <<<(NNODES + 255) / 256, 256, 0, sB>>>(NNODES);                  // 4 side
    scan_k    <<<1, 1024, 0, sB>>>();                                          // 5 side
    csr_fill_k<<<(NEDGES + 255) / 256, 256, 0, sB>>>(src, dst, NEDGES);        // 6 side

    // Join: agg1 needs CSR + dinv + hs.
    cudaEventRecord(evJoin, sB);
    cudaStreamWaitEvent(0, evJoin, 0);

    agg_k<<<agg_grid, 256>>>(b1, h1, 1);                                       // 7
    gemm_mma_k<false><<<gemm_grid, 256>>>(h1, wt2, hs, NNODES, CDIM);          // 8
    agg_k<<<agg_grid, 256>>>(b2, (float*)d_out, 0);                            // 9
}